// round 1
// baseline (speedup 1.0000x reference)
#include <cuda_runtime.h>
#include <math.h>

#define TT   512
#define BB   64
#define DD   1024
#define NBK  16
#define NST  64
#define TOKN (TT*BB)                 // 32768 tokens
#define LISTCAP (TOKN*2 + NBK*64)    // 66560 (padded expert lists)
#define NTILES  (LISTCAP/64)         // 1040
#define OUT_OFF ((size_t)TOKN*NST)   // outputs come first, then S_final

// ---------------- scratch (static device memory; no allocs allowed) -------
__device__ float    g_logits[TOKN*NBK];
__device__ float    g_q[TOKN*NST];
__device__ float    g_w[TOKN*NBK];
__device__ int      g_sel[TOKN*2];
__device__ float    g_selout[(size_t)TOKN*2*192];      // per (token,slot): k[64] v[64] beta_pre[64]
__device__ float    g_partial[(size_t)TOKN*NBK*NST];   // w_c * block_out, reduced later
__device__ unsigned g_list[LISTCAP];
__device__ int      g_counts[NBK];
__device__ int      g_base[NBK+1];
__device__ int      g_cursor[NBK];

// ---------------- FFMA-only transcendentals (avoid MUFU throughput wall) --
__device__ __forceinline__ float fexp2_fast(float t) {
    t = fminf(fmaxf(t, -80.0f), 80.0f);
    float fl = floorf(t);
    float f  = t - fl;                 // f in [0,1)
    float p  = 1.54035304e-4f;
    p = fmaf(p, f, 1.33335581e-3f);
    p = fmaf(p, f, 9.61812911e-3f);
    p = fmaf(p, f, 5.55041087e-2f);
    p = fmaf(p, f, 2.40226507e-1f);
    p = fmaf(p, f, 6.93147181e-1f);
    p = fmaf(p, f, 1.0f);
    int ei = (int)fl;
    float sc = __int_as_float((ei + 127) << 23);
    return p * sc;
}
__device__ __forceinline__ float frcp_pos(float z) {
    // magic-constant seed + 3 Newton iterations -> ~full fp32 precision, no MUFU
    float y = __int_as_float(0x7EF311C3 - __float_as_int(z));
    y = y * fmaf(-z, y, 2.0f);
    y = y * fmaf(-z, y, 2.0f);
    y = y * fmaf(-z, y, 2.0f);
    return y;
}
__device__ __forceinline__ float fsigmoid(float x) {
    float E = fexp2_fast(-1.44269504f * x);
    return frcp_pos(1.0f + E);
}
__device__ __forceinline__ float ftanh_fast(float x) {
    float E = fexp2_fast(2.88539008f * x);   // e^{2x}
    return 1.0f - 2.0f * frcp_pos(1.0f + E);
}

// ---------------- K0: init lists/counters (graph replays need this) -------
__global__ void k_init() {
    int idx = blockIdx.x * 256 + threadIdx.x;
    if (idx < LISTCAP) g_list[idx] = 0xFFFFFFFFu;
    if (idx < NBK)     g_counts[idx] = 0;
}

// ---------------- K1: dense GEMM for router logits (16) + q (64) ---------
// Y[tok, 0..15] = x . W_router^T ; Y[tok, 16..79] = x . W_q^T
__global__ __launch_bounds__(256) void k_gemm_rq(const float* __restrict__ x,
                                                 const float* __restrict__ Wr,
                                                 const float* __restrict__ Wq) {
    __shared__ float Xs[32][64];   // [k][m] transposed for vector reads
    __shared__ float Ws[32][80];   // [k][n]
    const int tid = threadIdx.x;
    const int ty = tid >> 4, tx = tid & 15;
    const int row0 = blockIdx.x * 64;
    float acc[4][5];
#pragma unroll
    for (int i = 0; i < 4; i++)
#pragma unroll
        for (int j = 0; j < 5; j++) acc[i][j] = 0.0f;

    for (int kt = 0; kt < DD; kt += 32) {
#pragma unroll
        for (int it = 0; it < 2; it++) {           // 512 float4 of X
            int idx = tid + it * 256;
            int r = idx >> 3, c4 = idx & 7;
            float4 v = *(const float4*)(x + (size_t)(row0 + r) * DD + kt + c4 * 4);
            Xs[c4*4+0][r] = v.x; Xs[c4*4+1][r] = v.y;
            Xs[c4*4+2][r] = v.z; Xs[c4*4+3][r] = v.w;
        }
#pragma unroll
        for (int it = 0; it < 3; it++) {           // 640 float4 of W
            int idx = tid + it * 256;
            if (idx < 640) {
                int r = idx >> 3, c4 = idx & 7;
                const float* wp = (r < 16) ? (Wr + (size_t)r * DD)
                                           : (Wq + (size_t)(r - 16) * DD);
                float4 v = *(const float4*)(wp + kt + c4 * 4);
                Ws[c4*4+0][r] = v.x; Ws[c4*4+1][r] = v.y;
                Ws[c4*4+2][r] = v.z; Ws[c4*4+3][r] = v.w;
            }
        }
        __syncthreads();
#pragma unroll
        for (int kk = 0; kk < 32; kk++) {
            float4 a = *(const float4*)&Xs[kk][ty * 4];
            float b0 = Ws[kk][tx*5+0], b1 = Ws[kk][tx*5+1], b2 = Ws[kk][tx*5+2];
            float b3 = Ws[kk][tx*5+3], b4 = Ws[kk][tx*5+4];
            acc[0][0] = fmaf(a.x, b0, acc[0][0]); acc[0][1] = fmaf(a.x, b1, acc[0][1]);
            acc[0][2] = fmaf(a.x, b2, acc[0][2]); acc[0][3] = fmaf(a.x, b3, acc[0][3]);
            acc[0][4] = fmaf(a.x, b4, acc[0][4]);
            acc[1][0] = fmaf(a.y, b0, acc[1][0]); acc[1][1] = fmaf(a.y, b1, acc[1][1]);
            acc[1][2] = fmaf(a.y, b2, acc[1][2]); acc[1][3] = fmaf(a.y, b3, acc[1][3]);
            acc[1][4] = fmaf(a.y, b4, acc[1][4]);
            acc[2][0] = fmaf(a.z, b0, acc[2][0]); acc[2][1] = fmaf(a.z, b1, acc[2][1]);
            acc[2][2] = fmaf(a.z, b2, acc[2][2]); acc[2][3] = fmaf(a.z, b3, acc[2][3]);
            acc[2][4] = fmaf(a.z, b4, acc[2][4]);
            acc[3][0] = fmaf(a.w, b0, acc[3][0]); acc[3][1] = fmaf(a.w, b1, acc[3][1]);
            acc[3][2] = fmaf(a.w, b2, acc[3][2]); acc[3][3] = fmaf(a.w, b3, acc[3][3]);
            acc[3][4] = fmaf(a.w, b4, acc[3][4]);
        }
        __syncthreads();
    }
#pragma unroll
    for (int i = 0; i < 4; i++) {
        int tokr = row0 + ty * 4 + i;
#pragma unroll
        for (int j = 0; j < 5; j++) {
            int col = tx * 5 + j;
            float v = acc[i][j];
            if (col < 16) g_logits[(size_t)tokr * 16 + col] = v;
            else          g_q[(size_t)tokr * 64 + (col - 16)] = v;
        }
    }
}

// ---------------- K2: top-2 + softmax + expert histogram ------------------
__global__ void k_topk() {
    int tok = blockIdx.x * 256 + threadIdx.x;
    if (tok >= TOKN) return;
    float lg[16];
#pragma unroll
    for (int c = 0; c < 16; c++) lg[c] = g_logits[(size_t)tok * 16 + c];
    float v0 = -1e30f, v1 = -1e30f; int i0 = 0, i1 = 0;
#pragma unroll
    for (int c = 0; c < 16; c++) {
        float l = lg[c];
        if (l > v0) { v1 = v0; i1 = i0; v0 = l; i0 = c; }
        else if (l > v1) { v1 = l; i1 = c; }
    }
    float s = 0.0f, w[16];
#pragma unroll
    for (int c = 0; c < 16; c++) { float e = __expf(lg[c] - v0); w[c] = e; s += e; }
    float rs = 1.0f / s;
#pragma unroll
    for (int c = 0; c < 16; c++) g_w[(size_t)tok * 16 + c] = w[c] * rs;
    g_sel[tok * 2 + 0] = i0;
    g_sel[tok * 2 + 1] = i1;
    atomicAdd(&g_counts[i0], 1);
    atomicAdd(&g_counts[i1], 1);
}

// ---------------- K3: prefix (64-aligned bases per expert) ----------------
__global__ void k_prefix() {
    if (threadIdx.x == 0 && blockIdx.x == 0) {
        int b = 0;
        for (int e = 0; e < NBK; e++) {
            g_base[e] = b; g_cursor[e] = b;
            b += ((g_counts[e] + 63) >> 6) << 6;
        }
        g_base[NBK] = b;
    }
}

// ---------------- K4: fill per-expert token lists --------------------------
__global__ void k_fill() {
    int idx = blockIdx.x * 256 + threadIdx.x;   // idx = tok*2 + slot
    if (idx < TOKN * 2) {
        int e = g_sel[idx];
        int pos = atomicAdd(&g_cursor[e], 1);
        g_list[pos] = (unsigned)idx;
    }
}

// ---------------- K5: grouped expert GEMM (gathered 64x192x1024) ----------
__global__ __launch_bounds__(256) void k_group_gemm(const float* __restrict__ x,
                                                    const float* __restrict__ Wkv,
                                                    const float* __restrict__ Wbeta) {
    __shared__ float Xs[32][64];
    __shared__ float Ws[32][192];
    __shared__ unsigned s_ent[64];
    __shared__ int s_e;
    const int tid = threadIdx.x;
    const int tile0 = blockIdx.x * 64;
    if (tid == 0) {
        int e = -1;
#pragma unroll
        for (int k = 0; k < NBK; k++)
            if (tile0 >= g_base[k] && tile0 < g_base[k + 1]) e = k;
        s_e = e;
    }
    if (tid < 64) s_ent[tid] = g_list[tile0 + tid];
    __syncthreads();
    const int e = s_e;
    if (e < 0) return;   // padding tile beyond all experts

    const int ty = tid >> 4, tx = tid & 15;
    float acc[4][12];
#pragma unroll
    for (int i = 0; i < 4; i++)
#pragma unroll
        for (int j = 0; j < 12; j++) acc[i][j] = 0.0f;

    for (int kt = 0; kt < DD; kt += 32) {
#pragma unroll
        for (int it = 0; it < 2; it++) {   // gather X rows (512 float4)
            int idx = tid + it * 256;
            int r = idx >> 3, c4 = idx & 7;
            unsigned ent = s_ent[r];
            float4 v = make_float4(0.f, 0.f, 0.f, 0.f);
            if (ent != 0xFFFFFFFFu) {
                int tok = (int)(ent >> 1);
                v = *(const float4*)(x + (size_t)tok * DD + kt + c4 * 4);
            }
            Xs[c4*4+0][r] = v.x; Xs[c4*4+1][r] = v.y;
            Xs[c4*4+2][r] = v.z; Xs[c4*4+3][r] = v.w;
        }
#pragma unroll
        for (int it = 0; it < 6; it++) {   // expert weights (1536 float4)
            int idx = tid + it * 256;
            int r = idx >> 3, c4 = idx & 7;
            const float* wp = (r < 128) ? (Wkv  + ((size_t)e * 128 + r) * DD)
                                        : (Wbeta + ((size_t)e * 64 + (r - 128)) * DD);
            float4 v = *(const float4*)(wp + kt + c4 * 4);
            Ws[c4*4+0][r] = v.x; Ws[c4*4+1][r] = v.y;
            Ws[c4*4+2][r] = v.z; Ws[c4*4+3][r] = v.w;
        }
        __syncthreads();
#pragma unroll
        for (int kk = 0; kk < 32; kk++) {
            float4 a  = *(const float4*)&Xs[kk][ty * 4];
            float4 b0 = *(const float4*)&Ws[kk][tx * 12 + 0];
            float4 b1 = *(const float4*)&Ws[kk][tx * 12 + 4];
            float4 b2 = *(const float4*)&Ws[kk][tx * 12 + 8];
            float av[4] = {a.x, a.y, a.z, a.w};
            float bv[12] = {b0.x,b0.y,b0.z,b0.w, b1.x,b1.y,b1.z,b1.w, b2.x,b2.y,b2.z,b2.w};
#pragma unroll
            for (int i = 0; i < 4; i++)
#pragma unroll
                for (int j = 0; j < 12; j++)
                    acc[i][j] = fmaf(av[i], bv[j], acc[i][j]);
        }
        __syncthreads();
    }
#pragma unroll
    for (int i = 0; i < 4; i++) {
        unsigned ent = s_ent[ty * 4 + i];
        if (ent == 0xFFFFFFFFu) continue;
        float* dst = g_selout + (size_t)ent * 192 + tx * 12;
#pragma unroll
        for (int j = 0; j < 12; j++) dst[j] = acc[i][j];
    }
}

// ---------------- K6: recurrent scan, one CTA per (batch, block) ----------
__global__ __launch_bounds__(64) void k_scan(const float* __restrict__ b_beta,
                                             float* __restrict__ out) {
    const int bc = blockIdx.x;
    const int b = bc >> 4, c = bc & 15;
    const int tid = threadIdx.x;      // S row index i

    float S[64];
#pragma unroll
    for (int j = 0; j < 64; j++) S[j] = 0.0f;
    const float bb = b_beta[c * 64 + tid];

    __shared__ float sq[64];
    __shared__ float sk[64];
    __shared__ float red[64];
    __shared__ int ssel0, ssel1;
    __shared__ float sw;

    for (int t = 0; t < TT; t++) {
        const int tok = t * BB + b;
        sq[tid] = g_q[(size_t)tok * 64 + tid];
        if (tid == 0) {
            ssel0 = g_sel[tok * 2 + 0];
            ssel1 = g_sel[tok * 2 + 1];
            sw = g_w[(size_t)tok * 16 + c];
        }
        __syncthreads();
        const int slot = (ssel0 == c) ? 0 : ((ssel1 == c) ? 1 : -1);
        if (slot >= 0) {   // CTA-uniform branch
            const float* sel = g_selout + ((size_t)tok * 2 + slot) * 192;
            float kk   = sel[tid];
            float vv   = sel[64 + tid];
            float bpre = sel[128 + tid];
            red[tid] = kk * kk;
            __syncthreads();
            if (tid < 32) red[tid] += red[tid + 32]; __syncthreads();
            if (tid < 16) red[tid] += red[tid + 16]; __syncthreads();
            if (tid < 8)  red[tid] += red[tid + 8];  __syncthreads();
            if (tid < 4)  red[tid] += red[tid + 4];  __syncthreads();
            if (tid < 2)  red[tid] += red[tid + 2];  __syncthreads();
            if (tid < 1)  red[0]   += red[1];        __syncthreads();
            float rn = 1.0f / (sqrtf(red[0]) + 1e-6f);
            sk[tid] = kk * rn;
            __syncthreads();
            float r0 = 0.f, r1 = 0.f, r2 = 0.f, r3 = 0.f;
#pragma unroll
            for (int j = 0; j < 64; j += 4) {
                r0 = fmaf(S[j+0], sk[j+0], r0);
                r1 = fmaf(S[j+1], sk[j+1], r1);
                r2 = fmaf(S[j+2], sk[j+2], r2);
                r3 = fmaf(S[j+3], sk[j+3], r3);
            }
            float retr  = (r0 + r1) + (r2 + r3);
            float delta = vv - retr;
            float beta  = fsigmoid(bpre + bb);
#pragma unroll
            for (int j = 0; j < 64; j++)
                S[j] = ftanh_fast(fmaf(beta, S[j], delta * sk[j]));
        }
        // Sq[i] = S[i][:] . q ; block_out = Sq^2 * sigmoid(Sq)
        float a0 = 0.f, a1 = 0.f, a2 = 0.f, a3 = 0.f;
#pragma unroll
        for (int j = 0; j < 64; j += 4) {
            a0 = fmaf(S[j+0], sq[j+0], a0);
            a1 = fmaf(S[j+1], sq[j+1], a1);
            a2 = fmaf(S[j+2], sq[j+2], a2);
            a3 = fmaf(S[j+3], sq[j+3], a3);
        }
        float sqv = (a0 + a1) + (a2 + a3);
        float bo = sqv * sqv * fsigmoid(sqv);
        g_partial[((size_t)tok * 16 + c) * 64 + tid] = sw * bo;
        __syncthreads();   // protect sq/sel/sw before next step
    }
    // S_final[b][c][i][j]
    float* Sf = out + OUT_OFF;
    size_t base = (((size_t)b * 16 + c) * 64 + tid) * 64;
#pragma unroll
    for (int j = 0; j < 64; j++) Sf[base + j] = S[j];
}

// ---------------- K7: reduce over blocks -> outputs ------------------------
__global__ void k_reduce(float* __restrict__ out) {
    int idx = blockIdx.x * 256 + threadIdx.x;     // over TOKN*64
    int tok = idx >> 6, i = idx & 63;
    float s = 0.0f;
#pragma unroll
    for (int c = 0; c < 16; c++)
        s += g_partial[((size_t)tok * 16 + c) * 64 + i];
    out[idx] = s;   // outputs[t][b][i], tok = t*BATCH + b
}

// ---------------- launch ---------------------------------------------------
extern "C" void kernel_launch(void* const* d_in, const int* in_sizes, int n_in,
                              void* d_out, int out_size) {
    const float* x    = (const float*)d_in[0];
    const float* Wr   = (const float*)d_in[1];
    const float* Wkv  = (const float*)d_in[2];
    const float* Wb   = (const float*)d_in[3];
    const float* bb   = (const float*)d_in[4];
    const float* Wq   = (const float*)d_in[5];
    float* out = (float*)d_out;
    (void)in_sizes; (void)n_in; (void)out_size;

    k_init<<<(LISTCAP + 255) / 256, 256>>>();
    k_gemm_rq<<<TOKN / 64, 256>>>(x, Wr, Wq);
    k_topk<<<TOKN / 256, 256>>>();
    k_prefix<<<1, 32>>>();
    k_fill<<<(TOKN * 2) / 256, 256>>>();
    k_group_gemm<<<NTILES, 256>>>(x, Wkv, Wb);
    k_scan<<<BB * NBK, 64>>>(bb, out);
    k_reduce<<<(TOKN * 64) / 256, 256>>>(out);
}

// round 3
// speedup vs baseline: 1.1620x; 1.1620x over previous
#include <cuda_runtime.h>
#include <math.h>
#include <stdint.h>

#define TT   512
#define BB   64
#define DD   1024
#define NBK  16
#define TOKN (TT*BB)                 // 32768 tokens
#define CAP  8192                    // fixed per-expert list capacity
#define NLIST (NBK*CAP)
#define OUT_OFF ((size_t)TOKN*64)

// ---------------- scratch ---------------------------------------------------
__device__ float    g_logits[TOKN*NBK];
__device__ float    g_q[(size_t)TOKN*64];
__device__ float    g_w[TOKN*NBK];
__device__ int      g_sel[TOKN*2];
__device__ float    g_selout[(size_t)TOKN*2*192];    // per (token,slot): k[64] v[64] beta_pre[64]
__device__ float    g_partial[(size_t)TOKN*NBK*64];
__device__ unsigned g_list[NLIST];
__device__ int      g_cursor[NBK];

// ---------------- fast math (MUFU + 1 Newton) -------------------------------
__device__ __forceinline__ float ex2a(float x){ float r; asm("ex2.approx.f32 %0,%1;":"=f"(r):"f"(x)); return r; }
__device__ __forceinline__ float rcpa(float x){ float r; asm("rcp.approx.f32 %0,%1;":"=f"(r):"f"(x)); return r; }
__device__ __forceinline__ float fast_rcp(float z){ float y = rcpa(z); return y * fmaf(-z, y, 2.0f); }
__device__ __forceinline__ float fsig(float x){ float E = ex2a(-1.44269504f * x); return fast_rcp(1.0f + E); }
__device__ __forceinline__ float ftanh(float x){ float E = ex2a(2.88539008f * x); return fmaf(-2.0f, fast_rcp(1.0f + E), 1.0f); }

__device__ __forceinline__ uint32_t f2tf(float f){ uint32_t r; asm("cvt.rna.tf32.f32 %0,%1;":"=r"(r):"f"(f)); return r; }

__device__ __forceinline__ void mma_tf32(float4 &d, const uint4 &a, const uint2 &b){
    asm volatile("mma.sync.aligned.m16n8k8.row.col.f32.tf32.tf32.f32 "
                 "{%0,%1,%2,%3},{%4,%5,%6,%7},{%8,%9},{%0,%1,%2,%3};"
                 : "+f"(d.x), "+f"(d.y), "+f"(d.z), "+f"(d.w)
                 : "r"(a.x), "r"(a.y), "r"(a.z), "r"(a.w), "r"(b.x), "r"(b.y));
}

// ---------------- K1: init lists/cursors ------------------------------------
__global__ void k_init() {
    int i = blockIdx.x * 256 + threadIdx.x;
    if (i < NLIST) g_list[i] = 0xFFFFFFFFu;
    if (i < NBK)   g_cursor[i] = i * CAP;
}

// ---------------- K2: dense fp32 GEMM: router logits (16) + q (64) ----------
__global__ __launch_bounds__(256) void k_gemm_rq(const float* __restrict__ x,
                                                 const float* __restrict__ Wr,
                                                 const float* __restrict__ Wq) {
    __shared__ float Xs[32][64];
    __shared__ float Ws[32][80];
    const int tid = threadIdx.x;
    const int ty = tid >> 4, tx = tid & 15;
    const int row0 = blockIdx.x * 64;
    float acc[4][5];
#pragma unroll
    for (int i = 0; i < 4; i++)
#pragma unroll
        for (int j = 0; j < 5; j++) acc[i][j] = 0.0f;

    for (int kt = 0; kt < DD; kt += 32) {
#pragma unroll
        for (int it = 0; it < 2; it++) {
            int idx = tid + it * 256;
            int r = idx >> 3, c4 = idx & 7;
            float4 v = *(const float4*)(x + (size_t)(row0 + r) * DD + kt + c4 * 4);
            Xs[c4*4+0][r] = v.x; Xs[c4*4+1][r] = v.y;
            Xs[c4*4+2][r] = v.z; Xs[c4*4+3][r] = v.w;
        }
#pragma unroll
        for (int it = 0; it < 3; it++) {
            int idx = tid + it * 256;
            if (idx < 640) {
                int r = idx >> 3, c4 = idx & 7;
                const float* wp = (r < 16) ? (Wr + (size_t)r * DD)
                                           : (Wq + (size_t)(r - 16) * DD);
                float4 v = *(const float4*)(wp + kt + c4 * 4);
                Ws[c4*4+0][r] = v.x; Ws[c4*4+1][r] = v.y;
                Ws[c4*4+2][r] = v.z; Ws[c4*4+3][r] = v.w;
            }
        }
        __syncthreads();
#pragma unroll
        for (int kk = 0; kk < 32; kk++) {
            float4 a = *(const float4*)&Xs[kk][ty * 4];
            float b0 = Ws[kk][tx*5+0], b1 = Ws[kk][tx*5+1], b2 = Ws[kk][tx*5+2];
            float b3 = Ws[kk][tx*5+3], b4 = Ws[kk][tx*5+4];
            float av[4] = {a.x, a.y, a.z, a.w};
#pragma unroll
            for (int i = 0; i < 4; i++) {
                acc[i][0] = fmaf(av[i], b0, acc[i][0]);
                acc[i][1] = fmaf(av[i], b1, acc[i][1]);
                acc[i][2] = fmaf(av[i], b2, acc[i][2]);
                acc[i][3] = fmaf(av[i], b3, acc[i][3]);
                acc[i][4] = fmaf(av[i], b4, acc[i][4]);
            }
        }
        __syncthreads();
    }
#pragma unroll
    for (int i = 0; i < 4; i++) {
        int tokr = row0 + ty * 4 + i;
#pragma unroll
        for (int j = 0; j < 5; j++) {
            int col = tx * 5 + j;
            float v = acc[i][j];
            if (col < 16) g_logits[(size_t)tokr * 16 + col] = v;
            else          g_q[(size_t)tokr * 64 + (col - 16)] = v;
        }
    }
}

// ---------------- K3: top-2 + softmax + direct list fill ---------------------
__global__ void k_topk_fill() {
    int tok = blockIdx.x * 256 + threadIdx.x;
    if (tok >= TOKN) return;
    float lg[16];
#pragma unroll
    for (int c = 0; c < 16; c++) lg[c] = g_logits[(size_t)tok * 16 + c];
    float v0 = -1e30f, v1 = -1e30f; int i0 = 0, i1 = 0;
#pragma unroll
    for (int c = 0; c < 16; c++) {
        float l = lg[c];
        if (l > v0) { v1 = v0; i1 = i0; v0 = l; i0 = c; }
        else if (l > v1) { v1 = l; i1 = c; }
    }
    float s = 0.0f, w[16];
#pragma unroll
    for (int c = 0; c < 16; c++) { float e = __expf(lg[c] - v0); w[c] = e; s += e; }
    float rs = 1.0f / s;
#pragma unroll
    for (int c = 0; c < 16; c++) g_w[(size_t)tok * 16 + c] = w[c] * rs;
    g_sel[tok * 2 + 0] = i0;
    g_sel[tok * 2 + 1] = i1;
    int p0 = atomicAdd(&g_cursor[i0], 1); g_list[p0] = (unsigned)(tok * 2);
    int p1 = atomicAdd(&g_cursor[i1], 1); g_list[p1] = (unsigned)(tok * 2 + 1);
}

// ---------------- K4: grouped tf32 tensor-core GEMM (3-mma fp32 split) ------
// Tile: 64 gathered tokens x 192 cols x KC=16 per iter. 8 warps = 2(M) x 4(N).
__global__ __launch_bounds__(256, 2) void k_ggemm(const float* __restrict__ x,
                                                  const float* __restrict__ Wkv,
                                                  const float* __restrict__ Wbeta) {
    // fragment-packed smem: A[a-tile 4][s 2][lane 32][reg 4], B[b-tile 24][s 2][lane 32][reg 2]
    __shared__ uint32_t Ah[4*2*32*4], Al[4*2*32*4];
    __shared__ uint32_t Bh[24*2*32*2], Bl[24*2*32*2];
    __shared__ unsigned s_ent[64];

    const int tid = threadIdx.x;
    const int e = blockIdx.x >> 7;                 // 128 tiles per expert
    const int lofs = e * CAP + (blockIdx.x & 127) * 64;
    if (tid < 64) s_ent[tid] = g_list[lofs + tid];
    __syncthreads();
    if (s_ent[0] == 0xFFFFFFFFu) return;           // lists fill contiguously

    const int warp = tid >> 5, lane = tid & 31;
    const int wm = warp >> 2, wn = warp & 3;

    float4 acc[2][6];
#pragma unroll
    for (int i = 0; i < 2; i++)
#pragma unroll
        for (int j = 0; j < 6; j++) acc[i][j] = make_float4(0.f, 0.f, 0.f, 0.f);

    // X-staging indices (per thread: one float4 = 4 consecutive k of one row)
    const int xrow = tid >> 2, xk0 = (tid & 3) * 4;
    const unsigned xent = s_ent[xrow];
    const float* xp = (xent != 0xFFFFFFFFu) ? (x + (size_t)(xent >> 1) * DD + xk0) : nullptr;
    const int xs = xk0 >> 3;
    const int xreg = ((xk0 & 4) ? 2 : 0) + (((xrow & 15) >= 8) ? 1 : 0);
    const int xbase = ((((xrow >> 4) * 2 + xs) * 32 + ((xrow & 7) << 2)) << 2) + xreg;

    for (int kt = 0; kt < DD; kt += 16) {
        // stage X (64 rows x 16 k)
        {
            float4 v = make_float4(0.f, 0.f, 0.f, 0.f);
            if (xp) v = *(const float4*)(xp + kt);
            float vv[4] = {v.x, v.y, v.z, v.w};
#pragma unroll
            for (int j = 0; j < 4; j++) {
                uint32_t h = f2tf(vv[j]);
                Ah[xbase + (j << 2)] = h;
                Al[xbase + (j << 2)] = f2tf(vv[j] - __uint_as_float(h));
            }
        }
        // stage W (192 rows x 16 k) : 768 float4, 3 per thread
#pragma unroll
        for (int it = 0; it < 3; it++) {
            int fi = tid + it * 256;
            int row = fi >> 2, k0 = (fi & 3) * 4;
            const float* wp = (row < 128) ? (Wkv + ((size_t)e * 128 + row) * DD)
                                          : (Wbeta + ((size_t)e * 64 + (row - 128)) * DD);
            float4 v = *(const float4*)(wp + kt + k0);
            int s = k0 >> 3, reg = (k0 & 4) ? 1 : 0;
            int base = ((((row >> 3) * 2 + s) * 32 + ((row & 7) << 2)) << 1) + reg;
            float vv[4] = {v.x, v.y, v.z, v.w};
#pragma unroll
            for (int j = 0; j < 4; j++) {
                uint32_t h = f2tf(vv[j]);
                Bh[base + (j << 1)] = h;
                Bl[base + (j << 1)] = f2tf(vv[j] - __uint_as_float(h));
            }
        }
        __syncthreads();
#pragma unroll
        for (int s = 0; s < 2; s++) {
            uint4 ah[2], al[2];
#pragma unroll
            for (int mi = 0; mi < 2; mi++) {
                int idx = ((((wm * 2 + mi) * 2 + s) * 32 + lane) << 2);
                ah[mi] = *(const uint4*)&Ah[idx];
                al[mi] = *(const uint4*)&Al[idx];
            }
#pragma unroll
            for (int ni = 0; ni < 6; ni++) {
                int idx = ((((wn * 6 + ni) * 2 + s) * 32 + lane) << 1);
                uint2 bh = *(const uint2*)&Bh[idx];
                uint2 bl = *(const uint2*)&Bl[idx];
#pragma unroll
                for (int mi = 0; mi < 2; mi++) {
                    mma_tf32(acc[mi][ni], ah[mi], bh);   // hi*hi
                    mma_tf32(acc[mi][ni], ah[mi], bl);   // hi*lo
                    mma_tf32(acc[mi][ni], al[mi], bh);   // lo*hi
                }
            }
        }
        __syncthreads();
    }
    // epilogue: scatter to g_selout
#pragma unroll
    for (int mi = 0; mi < 2; mi++) {
        int r0 = wm * 32 + mi * 16 + (lane >> 2);
        unsigned e0 = s_ent[r0], e1 = s_ent[r0 + 8];
#pragma unroll
        for (int ni = 0; ni < 6; ni++) {
            int c0 = wn * 48 + ni * 8 + ((lane & 3) << 1);
            if (e0 != 0xFFFFFFFFu)
                *(float2*)&g_selout[(size_t)e0 * 192 + c0] = make_float2(acc[mi][ni].x, acc[mi][ni].y);
            if (e1 != 0xFFFFFFFFu)
                *(float2*)&g_selout[(size_t)e1 * 192 + c0] = make_float2(acc[mi][ni].z, acc[mi][ni].w);
        }
    }
}

// ---------------- K5: recurrent scan -----------------------------------------
__global__ __launch_bounds__(64) void k_scan(const float* __restrict__ b_beta,
                                             float* __restrict__ out) {
    const int bc = blockIdx.x;
    const int b = bc >> 4, c = bc & 15;
    const int tid = threadIdx.x;

    float S[64];
#pragma unroll
    for (int j = 0; j < 64; j++) S[j] = 0.0f;
    const float bb = b_beta[c * 64 + tid];

    __shared__ float sq[2][64];
    __shared__ float sk[64];
    __shared__ float spart[2];
    __shared__ int   ssel[2][2];
    __shared__ float sww[2];

    for (int t = 0; t < TT; t++) {
        const int tok = t * BB + b;
        const int p = t & 1;
        sq[p][tid] = g_q[(size_t)tok * 64 + tid];
        if (tid == 0) {
            ssel[p][0] = g_sel[tok * 2 + 0];
            ssel[p][1] = g_sel[tok * 2 + 1];
            sww[p] = g_w[(size_t)tok * 16 + c];
        }
        __syncthreads();
        const int slot = (ssel[p][0] == c) ? 0 : ((ssel[p][1] == c) ? 1 : -1);
        if (slot >= 0) {   // CTA-uniform
            const float* sel = g_selout + ((size_t)tok * 2 + slot) * 192;
            float kk = sel[tid], vv = sel[64 + tid], bp = sel[128 + tid];
            float ps = kk * kk;
#pragma unroll
            for (int o = 16; o; o >>= 1) ps += __shfl_xor_sync(0xffffffffu, ps, o);
            if ((tid & 31) == 0) spart[tid >> 5] = ps;
            __syncthreads();
            float rn = 1.0f / (sqrtf(spart[0] + spart[1]) + 1e-6f);
            sk[tid] = kk * rn;
            __syncthreads();
            float r0 = 0.f, r1 = 0.f, r2 = 0.f, r3 = 0.f;
#pragma unroll
            for (int j = 0; j < 64; j += 4) {
                r0 = fmaf(S[j+0], sk[j+0], r0);
                r1 = fmaf(S[j+1], sk[j+1], r1);
                r2 = fmaf(S[j+2], sk[j+2], r2);
                r3 = fmaf(S[j+3], sk[j+3], r3);
            }
            float delta = vv - ((r0 + r1) + (r2 + r3));
            float beta = fsig(bp + bb);
#pragma unroll
            for (int j = 0; j < 64; j++)
                S[j] = ftanh(fmaf(beta, S[j], delta * sk[j]));
        }
        float a0 = 0.f, a1 = 0.f, a2 = 0.f, a3 = 0.f;
        const float* q = sq[p];
#pragma unroll
        for (int j = 0; j < 64; j += 4) {
            a0 = fmaf(S[j+0], q[j+0], a0);
            a1 = fmaf(S[j+1], q[j+1], a1);
            a2 = fmaf(S[j+2], q[j+2], a2);
            a3 = fmaf(S[j+3], q[j+3], a3);
        }
        float sv = (a0 + a1) + (a2 + a3);
        g_partial[((size_t)tok * 16 + c) * 64 + tid] = sww[p] * sv * sv * fsig(sv);
    }
    float* Sf = out + OUT_OFF;
    size_t base = (((size_t)b * 16 + c) * 64 + tid) * 64;
#pragma unroll
    for (int j = 0; j < 64; j++) Sf[base + j] = S[j];
}

// ---------------- K6: reduce over blocks -> outputs --------------------------
__global__ void k_reduce(float* __restrict__ out) {
    int idx = blockIdx.x * 256 + threadIdx.x;
    int tok = idx >> 6, i = idx & 63;
    float s = 0.0f;
#pragma unroll
    for (int c = 0; c < 16; c++)
        s += g_partial[((size_t)tok * 16 + c) * 64 + i];
    out[idx] = s;
}

// ---------------- launch -----------------------------------------------------
extern "C" void kernel_launch(void* const* d_in, const int* in_sizes, int n_in,
                              void* d_out, int out_size) {
    const float* x    = (const float*)d_in[0];
    const float* Wr   = (const float*)d_in[1];
    const float* Wkv  = (const float*)d_in[2];
    const float* Wb   = (const float*)d_in[3];
    const float* bb   = (const float*)d_in[4];
    const float* Wq   = (const float*)d_in[5];
    float* out = (float*)d_out;
    (void)in_sizes; (void)n_in; (void)out_size;

    k_init<<<NLIST / 256, 256>>>();
    k_gemm_rq<<<TOKN / 64, 256>>>(x, Wr, Wq);
    k_topk_fill<<<TOKN / 256, 256>>>();
    k_ggemm<<<NBK * (CAP / 64), 256>>>(x, Wkv, Wb);
    k_scan<<<BB * NBK, 64>>>(bb, out);
    k_reduce<<<(TOKN * 64) / 256, 256>>>(out);
}

// round 4
// speedup vs baseline: 1.4614x; 1.2577x over previous
#include <cuda_runtime.h>
#include <cuda_bf16.h>
#include <math.h>
#include <stdint.h>

#define TT   512
#define BB   64
#define DD   1024
#define NBK  16
#define TOKN (TT*BB)                 // 32768 tokens
#define CAP  8192                    // fixed per-expert list capacity
#define NLIST (NBK*CAP)
#define OUT_OFF ((size_t)TOKN*64)

// ---------------- scratch ---------------------------------------------------
__device__ float    g_logits[TOKN*NBK];
__device__ float    g_q[(size_t)TOKN*64];
__device__ float    g_w[TOKN*NBK];
__device__ int      g_sel[TOKN*2];
__device__ float    g_selout[(size_t)TOKN*2*192];    // per (token,slot): k[64] v[64] beta_pre[64]
__device__ float    g_partial[(size_t)TOKN*NBK*64];
__device__ unsigned g_list[NLIST];
__device__ int      g_cursor[NBK];

// ---------------- fast math --------------------------------------------------
__device__ __forceinline__ float ex2a(float x){ float r; asm("ex2.approx.f32 %0,%1;":"=f"(r):"f"(x)); return r; }
__device__ __forceinline__ float rcpa(float x){ float r; asm("rcp.approx.f32 %0,%1;":"=f"(r):"f"(x)); return r; }
__device__ __forceinline__ float fast_rcp(float z){ float y = rcpa(z); return y * fmaf(-z, y, 2.0f); }
__device__ __forceinline__ float fsig(float x){ float E = ex2a(-1.44269504f * x); return fast_rcp(1.0f + E); }
__device__ __forceinline__ float ftanh(float x){ float E = ex2a(2.88539008f * x); return fmaf(-2.0f, fast_rcp(1.0f + E), 1.0f); }

__device__ __forceinline__ uint32_t f2tf(float f){ uint32_t r; asm("cvt.rna.tf32.f32 %0,%1;":"=r"(r):"f"(f)); return r; }
__device__ __forceinline__ uint32_t bf16r(float f){ uint16_t r; asm("cvt.rn.bf16.f32 %0,%1;":"=h"(r):"f"(f)); return (uint32_t)r; }

// split-pack two floats (consecutive k) into hi/lo bf16x2 words
__device__ __forceinline__ void split_pack(float a, float b, uint32_t &hi, uint32_t &lo){
    uint32_t ha = bf16r(a), hb = bf16r(b);
    float ra = a - __uint_as_float(ha << 16);
    float rb = b - __uint_as_float(hb << 16);
    hi = ha | (hb << 16);
    lo = bf16r(ra) | (bf16r(rb) << 16);
}

__device__ __forceinline__ void mma_tf32(float4 &d, const uint4 &a, const uint2 &b){
    asm volatile("mma.sync.aligned.m16n8k8.row.col.f32.tf32.tf32.f32 "
                 "{%0,%1,%2,%3},{%4,%5,%6,%7},{%8,%9},{%0,%1,%2,%3};"
                 : "+f"(d.x), "+f"(d.y), "+f"(d.z), "+f"(d.w)
                 : "r"(a.x), "r"(a.y), "r"(a.z), "r"(a.w), "r"(b.x), "r"(b.y));
}
__device__ __forceinline__ void mma_bf16(float4 &d, const uint4 &a, const uint2 &b){
    asm volatile("mma.sync.aligned.m16n8k16.row.col.f32.bf16.bf16.f32 "
                 "{%0,%1,%2,%3},{%4,%5,%6,%7},{%8,%9},{%0,%1,%2,%3};"
                 : "+f"(d.x), "+f"(d.y), "+f"(d.z), "+f"(d.w)
                 : "r"(a.x), "r"(a.y), "r"(a.z), "r"(a.w), "r"(b.x), "r"(b.y));
}

// ---------------- K1: init lists/cursors ------------------------------------
__global__ void k_init() {
    int i = blockIdx.x * 256 + threadIdx.x;
    if (i < NLIST) g_list[i] = 0xFFFFFFFFu;
    if (i < NBK)   g_cursor[i] = i * CAP;
}

// ---------------- K2: router+q GEMM via tf32 3-split mma ---------------------
// M=64 (dense tokens) x N=80 x K=1024. 8 warps = 4(M) x 2(N), KC=16.
__global__ __launch_bounds__(256) void k_rq_mma(const float* __restrict__ x,
                                                const float* __restrict__ Wr,
                                                const float* __restrict__ Wq) {
    __shared__ uint32_t Ah[4*2*32*4], Al[4*2*32*4];     // [mtile][s][lane][reg]
    __shared__ uint32_t Bh[10*2*32*2], Bl[10*2*32*2];   // [ntile][s][lane][reg]

    const int tid = threadIdx.x;
    const int row0 = blockIdx.x * 64;
    const int warp = tid >> 5, lane = tid & 31;
    const int wm = warp >> 1, wn = warp & 1;

    float4 acc[5];
#pragma unroll
    for (int j = 0; j < 5; j++) acc[j] = make_float4(0.f, 0.f, 0.f, 0.f);

    const int xrow = tid >> 2, xk0 = (tid & 3) * 4;
    const float* xp = x + (size_t)(row0 + xrow) * DD + xk0;
    const int xs = xk0 >> 3;
    const int xreg = ((xk0 & 4) ? 2 : 0) + (((xrow & 15) >= 8) ? 1 : 0);
    const int xbase = ((((xrow >> 4) * 2 + xs) * 32 + ((xrow & 7) << 2)) << 2) + xreg;

    for (int kt = 0; kt < DD; kt += 16) {
        {   // stage X (64 x 16)
            float4 v = *(const float4*)(xp + kt);
            float vv[4] = {v.x, v.y, v.z, v.w};
#pragma unroll
            for (int j = 0; j < 4; j++) {
                uint32_t h = f2tf(vv[j]);
                Ah[xbase + (j << 2)] = h;
                Al[xbase + (j << 2)] = f2tf(vv[j] - __uint_as_float(h));
            }
        }
#pragma unroll
        for (int it = 0; it < 2; it++) {   // stage W (80 x 16): 320 float4
            int fi = tid + it * 256;
            if (fi < 320) {
                int row = fi >> 2, k0 = (fi & 3) * 4;
                const float* wp = (row < 16) ? (Wr + (size_t)row * DD)
                                             : (Wq + (size_t)(row - 16) * DD);
                float4 v = *(const float4*)(wp + kt + k0);
                int s = k0 >> 3, reg = (k0 & 4) ? 1 : 0;
                int base = ((((row >> 3) * 2 + s) * 32 + ((row & 7) << 2)) << 1) + reg;
                float vv[4] = {v.x, v.y, v.z, v.w};
#pragma unroll
                for (int j = 0; j < 4; j++) {
                    uint32_t h = f2tf(vv[j]);
                    Bh[base + (j << 1)] = h;
                    Bl[base + (j << 1)] = f2tf(vv[j] - __uint_as_float(h));
                }
            }
        }
        __syncthreads();
#pragma unroll
        for (int s = 0; s < 2; s++) {
            int aidx = (((wm * 2 + s) * 32 + lane) << 2);
            uint4 ah = *(const uint4*)&Ah[aidx];
            uint4 al = *(const uint4*)&Al[aidx];
#pragma unroll
            for (int ni = 0; ni < 5; ni++) {
                int bidx = ((((wn * 5 + ni) * 2 + s) * 32 + lane) << 1);
                uint2 bh = *(const uint2*)&Bh[bidx];
                uint2 bl = *(const uint2*)&Bl[bidx];
                mma_tf32(acc[ni], ah, bh);
                mma_tf32(acc[ni], ah, bl);
                mma_tf32(acc[ni], al, bh);
            }
        }
        __syncthreads();
    }
    // epilogue
    int r0 = row0 + wm * 16 + (lane >> 2);
#pragma unroll
    for (int ni = 0; ni < 5; ni++) {
        int c0 = wn * 40 + ni * 8 + ((lane & 3) << 1);
        if (c0 < 16) {
            *(float2*)&g_logits[(size_t)r0 * 16 + c0]       = make_float2(acc[ni].x, acc[ni].y);
            *(float2*)&g_logits[(size_t)(r0 + 8) * 16 + c0] = make_float2(acc[ni].z, acc[ni].w);
        } else {
            int c = c0 - 16;
            *(float2*)&g_q[(size_t)r0 * 64 + c]       = make_float2(acc[ni].x, acc[ni].y);
            *(float2*)&g_q[(size_t)(r0 + 8) * 64 + c] = make_float2(acc[ni].z, acc[ni].w);
        }
    }
}

// ---------------- K3: top-2 + softmax + direct list fill ---------------------
__global__ void k_topk_fill() {
    int tok = blockIdx.x * 256 + threadIdx.x;
    if (tok >= TOKN) return;
    float lg[16];
#pragma unroll
    for (int c = 0; c < 16; c++) lg[c] = g_logits[(size_t)tok * 16 + c];
    float v0 = -1e30f, v1 = -1e30f; int i0 = 0, i1 = 0;
#pragma unroll
    for (int c = 0; c < 16; c++) {
        float l = lg[c];
        if (l > v0) { v1 = v0; i1 = i0; v0 = l; i0 = c; }
        else if (l > v1) { v1 = l; i1 = c; }
    }
    float s = 0.0f, w[16];
#pragma unroll
    for (int c = 0; c < 16; c++) { float e = __expf(lg[c] - v0); w[c] = e; s += e; }
    float rs = 1.0f / s;
#pragma unroll
    for (int c = 0; c < 16; c++) g_w[(size_t)tok * 16 + c] = w[c] * rs;
    g_sel[tok * 2 + 0] = i0;
    g_sel[tok * 2 + 1] = i1;
    int p0 = atomicAdd(&g_cursor[i0], 1); g_list[p0] = (unsigned)(tok * 2);
    int p1 = atomicAdd(&g_cursor[i1], 1); g_list[p1] = (unsigned)(tok * 2 + 1);
}

// ---------------- K4: grouped bf16 3-split tensor GEMM -----------------------
// Tile 64 gathered tokens x 192 cols, KC=32. 8 warps = 2(M) x 4(N).
// SMEM fragment-packed: A[mtile4][kt2][hl2][lane32][reg4], B[nt24][kt2][hl2][lane32][reg2]
__global__ __launch_bounds__(256) void k_ggemm(const float* __restrict__ x,
                                               const float* __restrict__ Wkv,
                                               const float* __restrict__ Wbeta) {
    __shared__ uint32_t As[4][2][2][32][4];   // 8 KB
    __shared__ uint32_t Bs[24][2][2][32][2];  // 24 KB
    __shared__ unsigned s_ent[64];

    const int tid = threadIdx.x;
    const int e = blockIdx.x >> 7;
    const int lofs = e * CAP + (blockIdx.x & 127) * 64;
    if (tid < 64) s_ent[tid] = g_list[lofs + tid];
    __syncthreads();
    if (s_ent[0] == 0xFFFFFFFFu) return;

    const int warp = tid >> 5, lane = tid & 31;
    const int wm = warp >> 2, wn = warp & 3;

    float4 acc[2][6];
#pragma unroll
    for (int i = 0; i < 2; i++)
#pragma unroll
        for (int j = 0; j < 6; j++) acc[i][j] = make_float4(0.f, 0.f, 0.f, 0.f);

    // ---- A staging precompute: 2 units/thread, unit = (row-pair, k-pair) ----
    const int a_kp   = tid & 15;            // k = a_kp*2 within KC tile
    const int a_kti  = a_kp >> 3;
    const int a_lane = (((tid >> 4) & 7) << 2) | (a_kp & 3);
    const int a_reg  = (a_kp & 4) >> 1;     // 0 or 2
    const int a_mt0  = tid >> 7;            // unit0 mtile (0..1), unit1 = +2
    const int a_rlow = (tid >> 4) & 7;
    const float* a_p[4];                    // row0a,row1a,row0b,row1b
    {
        int rows[4] = { a_mt0 * 16 + a_rlow, a_mt0 * 16 + a_rlow + 8,
                        (a_mt0 + 2) * 16 + a_rlow, (a_mt0 + 2) * 16 + a_rlow + 8 };
#pragma unroll
        for (int i = 0; i < 4; i++) {
            unsigned ent = s_ent[rows[i]];
            a_p[i] = (ent != 0xFFFFFFFFu) ? (x + (size_t)(ent >> 1) * DD + a_kp * 2) : nullptr;
        }
    }
    // ---- B staging precompute: 6 units/thread (n = n0 + 32i) ----
    const int b_rem  = tid & 7;
    const int b_kti  = b_rem >> 2;
    const int b_k0   = b_kti * 16 + (b_rem & 3) * 2;
    const int b_lane = (((tid >> 3) & 7) << 2) | (b_rem & 3);
    const int b_n0   = tid >> 3;            // + 32*i
    const float* b_p[6];
#pragma unroll
    for (int i = 0; i < 6; i++) {
        int n = b_n0 + 32 * i;
        b_p[i] = ((n < 128) ? (Wkv + ((size_t)e * 128 + n) * DD)
                            : (Wbeta + ((size_t)e * 64 + (n - 128)) * DD)) + b_k0;
    }

    for (int kt = 0; kt < DD; kt += 32) {
        // stage A: units (a_mt0, a_mt0+2)
#pragma unroll
        for (int u = 0; u < 2; u++) {
            float2 v0 = make_float2(0.f, 0.f), v1 = v0;
            if (a_p[u*2+0]) v0 = *(const float2*)(a_p[u*2+0] + kt);
            if (a_p[u*2+1]) v1 = *(const float2*)(a_p[u*2+1] + kt);
            uint32_t h0, l0, h1, l1;
            split_pack(v0.x, v0.y, h0, l0);
            split_pack(v1.x, v1.y, h1, l1);
            int mt = a_mt0 + u * 2;
            *(uint2*)&As[mt][a_kti][0][a_lane][a_reg] = make_uint2(h0, h1);
            *(uint2*)&As[mt][a_kti][1][a_lane][a_reg] = make_uint2(l0, l1);
        }
        // stage B: 6 units, each covers (k0,k0+1) and (k0+8,k0+9) of row n
#pragma unroll
        for (int i = 0; i < 6; i++) {
            float2 v0 = *(const float2*)(b_p[i] + kt);
            float2 v1 = *(const float2*)(b_p[i] + kt + 8);
            uint32_t h0, l0, h1, l1;
            split_pack(v0.x, v0.y, h0, l0);
            split_pack(v1.x, v1.y, h1, l1);
            int nt = (b_n0 + 32 * i) >> 3;
            *(uint2*)&Bs[nt][b_kti][0][b_lane][0] = make_uint2(h0, h1);
            *(uint2*)&Bs[nt][b_kti][1][b_lane][0] = make_uint2(l0, l1);
        }
        __syncthreads();
#pragma unroll
        for (int kti = 0; kti < 2; kti++) {
            uint4 ah[2], al[2];
#pragma unroll
            for (int mi = 0; mi < 2; mi++) {
                ah[mi] = *(const uint4*)&As[wm * 2 + mi][kti][0][lane][0];
                al[mi] = *(const uint4*)&As[wm * 2 + mi][kti][1][lane][0];
            }
#pragma unroll
            for (int ni = 0; ni < 6; ni++) {
                uint2 bh = *(const uint2*)&Bs[wn * 6 + ni][kti][0][lane][0];
                uint2 bl = *(const uint2*)&Bs[wn * 6 + ni][kti][1][lane][0];
#pragma unroll
                for (int mi = 0; mi < 2; mi++) {
                    mma_bf16(acc[mi][ni], ah[mi], bh);   // hi*hi
                    mma_bf16(acc[mi][ni], ah[mi], bl);   // hi*lo
                    mma_bf16(acc[mi][ni], al[mi], bh);   // lo*hi
                }
            }
        }
        __syncthreads();
    }
    // epilogue: scatter to g_selout
#pragma unroll
    for (int mi = 0; mi < 2; mi++) {
        int r0 = wm * 32 + mi * 16 + (lane >> 2);
        unsigned e0 = s_ent[r0], e1 = s_ent[r0 + 8];
#pragma unroll
        for (int ni = 0; ni < 6; ni++) {
            int c0 = wn * 48 + ni * 8 + ((lane & 3) << 1);
            if (e0 != 0xFFFFFFFFu)
                *(float2*)&g_selout[(size_t)e0 * 192 + c0] = make_float2(acc[mi][ni].x, acc[mi][ni].y);
            if (e1 != 0xFFFFFFFFu)
                *(float2*)&g_selout[(size_t)e1 * 192 + c0] = make_float2(acc[mi][ni].z, acc[mi][ni].w);
        }
    }
}

// ---------------- K5: recurrent scan -----------------------------------------
__global__ __launch_bounds__(64) void k_scan(const float* __restrict__ b_beta,
                                             float* __restrict__ out) {
    const int bc = blockIdx.x;
    const int b = bc >> 4, c = bc & 15;
    const int tid = threadIdx.x;

    float S[64];
#pragma unroll
    for (int j = 0; j < 64; j++) S[j] = 0.0f;
    const float bb = b_beta[c * 64 + tid];

    __shared__ float sq[2][64];
    __shared__ float sk[64];
    __shared__ float spart[2];
    __shared__ int   ssel[2][2];
    __shared__ float sww[2];

    for (int t = 0; t < TT; t++) {
        const int tok = t * BB + b;
        const int p = t & 1;
        sq[p][tid] = g_q[(size_t)tok * 64 + tid];
        if (tid == 0) {
            ssel[p][0] = g_sel[tok * 2 + 0];
            ssel[p][1] = g_sel[tok * 2 + 1];
            sww[p] = g_w[(size_t)tok * 16 + c];
        }
        __syncthreads();
        const int slot = (ssel[p][0] == c) ? 0 : ((ssel[p][1] == c) ? 1 : -1);
        if (slot >= 0) {   // CTA-uniform
            const float* sel = g_selout + ((size_t)tok * 2 + slot) * 192;
            float kk = sel[tid], vv = sel[64 + tid], bp = sel[128 + tid];
            float ps = kk * kk;
#pragma unroll
            for (int o = 16; o; o >>= 1) ps += __shfl_xor_sync(0xffffffffu, ps, o);
            if ((tid & 31) == 0) spart[tid >> 5] = ps;
            __syncthreads();
            float rn = 1.0f / (sqrtf(spart[0] + spart[1]) + 1e-6f);
            sk[tid] = kk * rn;
            __syncthreads();
            float r0 = 0.f, r1 = 0.f, r2 = 0.f, r3 = 0.f;
#pragma unroll
            for (int j = 0; j < 64; j += 4) {
                r0 = fmaf(S[j+0], sk[j+0], r0);
                r1 = fmaf(S[j+1], sk[j+1], r1);
                r2 = fmaf(S[j+2], sk[j+2], r2);
                r3 = fmaf(S[j+3], sk[j+3], r3);
            }
            float delta = vv - ((r0 + r1) + (r2 + r3));
            float beta = fsig(bp + bb);
#pragma unroll
            for (int j = 0; j < 64; j++)
                S[j] = ftanh(fmaf(beta, S[j], delta * sk[j]));
        }
        float a0 = 0.f, a1 = 0.f, a2 = 0.f, a3 = 0.f;
        const float* q = sq[p];
#pragma unroll
        for (int j = 0; j < 64; j += 4) {
            a0 = fmaf(S[j+0], q[j+0], a0);
            a1 = fmaf(S[j+1], q[j+1], a1);
            a2 = fmaf(S[j+2], q[j+2], a2);
            a3 = fmaf(S[j+3], q[j+3], a3);
        }
        float sv = (a0 + a1) + (a2 + a3);
        g_partial[((size_t)tok * 16 + c) * 64 + tid] = sww[p] * sv * sv * fsig(sv);
    }
    float* Sf = out + OUT_OFF;
    size_t base = (((size_t)b * 16 + c) * 64 + tid) * 64;
#pragma unroll
    for (int j = 0; j < 64; j++) Sf[base + j] = S[j];
}

// ---------------- K6: reduce over blocks -> outputs --------------------------
__global__ void k_reduce(float* __restrict__ out) {
    int idx = blockIdx.x * 256 + threadIdx.x;
    int tok = idx >> 6, i = idx & 63;
    float s = 0.0f;
#pragma unroll
    for (int c = 0; c < 16; c++)
        s += g_partial[((size_t)tok * 16 + c) * 64 + i];
    out[idx] = s;
}

// ---------------- launch -----------------------------------------------------
extern "C" void kernel_launch(void* const* d_in, const int* in_sizes, int n_in,
                              void* d_out, int out_size) {
    const float* x    = (const float*)d_in[0];
    const float* Wr   = (const float*)d_in[1];
    const float* Wkv  = (const float*)d_in[2];
    const float* Wb   = (const float*)d_in[3];
    const float* bb   = (const float*)d_in[4];
    const float* Wq   = (const float*)d_in[5];
    float* out = (float*)d_out;
    (void)in_sizes; (void)n_in; (void)out_size;

    k_init<<<NLIST / 256, 256>>>();
    k_rq_mma<<<TOKN / 64, 256>>>(x, Wr, Wq);
    k_topk_fill<<<TOKN / 256, 256>>>();
    k_ggemm<<<NBK * (CAP / 64), 256>>>(x, Wkv, Wb);
    k_scan<<<BB * NBK, 64>>>(bb, out);
    k_reduce<<<(TOKN * 64) / 256, 256>>>(out);
}